// round 10
// baseline (speedup 1.0000x reference)
#include <cuda_runtime.h>
#include <cmath>

#define S_LEN  1024
#define BATCHN 128
#define IDIM   256
#define HDIM   512
#define ODIM   64

typedef unsigned long long ull;

// ---------- f32x2 packed helpers ----------
__device__ __forceinline__ ull splat2(float x) {
    ull r; asm("mov.b64 %0, {%1, %1};" : "=l"(r) : "f"(x)); return r;
}
__device__ __forceinline__ ull ffma2(ull a, ull b, ull c) {
    ull d; asm("fma.rn.f32x2 %0, %1, %2, %3;" : "=l"(d) : "l"(a), "l"(b), "l"(c)); return d;
}
__device__ __forceinline__ ull add2(ull a, ull b) {
    ull d; asm("add.rn.f32x2 %0, %1, %2;" : "=l"(d) : "l"(a), "l"(b)); return d;
}
__device__ __forceinline__ float2 upk2(ull v) {
    float2 f; asm("mov.b64 {%0, %1}, %2;" : "=f"(f.x), "=f"(f.y) : "l"(v)); return f;
}
__device__ __forceinline__ unsigned s2u32(const void* p) {
    unsigned a;
    asm("{ .reg .u64 t; cvta.to.shared.u64 t, %1; cvt.u32.u64 %0, t; }" : "=r"(a) : "l"(p));
    return a;
}
__device__ __forceinline__ unsigned mapa_rank(unsigned a, unsigned r) {
    unsigned d; asm("mapa.shared::cluster.u32 %0, %1, %2;" : "=r"(d) : "r"(a), "r"(r));
    return d;
}
__device__ __forceinline__ void bulk_s2c(unsigned dst, unsigned src, unsigned bytes,
                                         unsigned mbar) {
    asm volatile(
        "cp.async.bulk.shared::cluster.shared::cta.mbarrier::complete_tx::bytes "
        "[%0], [%1], %2, [%3];"
        :: "r"(dst), "r"(src), "r"(bytes), "r"(mbar) : "memory");
}
__device__ __forceinline__ void mbar_init(unsigned mbar, unsigned cnt) {
    asm volatile("mbarrier.init.shared.b64 [%0], %1;" :: "r"(mbar), "r"(cnt) : "memory");
}
__device__ __forceinline__ void mbar_expect_tx(unsigned mbar, unsigned bytes) {
    asm volatile("mbarrier.arrive.expect_tx.shared.b64 _, [%0], %1;"
                 :: "r"(mbar), "r"(bytes) : "memory");
}
__device__ __forceinline__ void mbar_wait_parity(unsigned mbar, unsigned parity) {
    asm volatile(
        "{\n\t"
        ".reg .pred P;\n"
        "LW_%=:\n\t"
        "mbarrier.try_wait.parity.acquire.cta.shared::cta.b64 P, [%0], %1, 0x989680;\n\t"
        "@P bra LD_%=;\n\t"
        "bra LW_%=;\n"
        "LD_%=:\n\t"
        "}"
        :: "r"(mbar), "r"(parity) : "memory");
}
__device__ __forceinline__ unsigned elect1() {
    unsigned p;
    asm volatile("{\n\t.reg .pred p;\n\telect.sync _|p, 0xFFFFFFFF;\n\t"
                 "selp.b32 %0, 1, 0, p;\n\t}" : "=r"(p));
    return p;
}
__device__ __forceinline__ void bar_sync_512(unsigned id) {
    asm volatile("bar.sync %0, 512;" :: "r"(id) : "memory");
}
__device__ __forceinline__ void bar_arrive_512(unsigned id) {
    asm volatile("bar.arrive %0, 512;" :: "r"(id) : "memory");
}
__device__ __forceinline__ void bar_sync_256(unsigned id) {
    asm volatile("bar.sync %0, 256;" :: "r"(id) : "memory");
}

// ---------- scratch (device globals: allocation-free rule) ----------
__device__ float g_xp[(size_t)BATCHN * S_LEN * HDIM];  // X@W_ih + b_hh, [b][s][h]
__device__ float g_h [(size_t)BATCHN * S_LEN * HDIM];  // hidden states,  [b][s][h]

// ============================================================================
// Kernel A: g_xp[M,512] = X[M,256] @ W_ih[256,512] + b_hh, M = 131072
// ============================================================================
__global__ void __launch_bounds__(256, 2) xproj_kernel(
    const float* __restrict__ X, const float* __restrict__ Wih,
    const float* __restrict__ bhh)
{
    __shared__ float As[128][17];
    __shared__ float Bs[16][128];
    const int tid = threadIdx.x;
    const int m0 = blockIdx.x * 128;
    const int n0 = blockIdx.y * 128;
    const int tx = tid & 15, ty = tid >> 4;

    ull acc[8][4];
#pragma unroll
    for (int i = 0; i < 8; i++)
#pragma unroll
        for (int j = 0; j < 4; j++) acc[i][j] = 0ull;

    for (int k0 = 0; k0 < IDIM; k0 += 16) {
#pragma unroll
        for (int i = 0; i < 2; i++) {
            int f4  = tid + i * 256;
            int row = f4 >> 2;
            int c4  = (f4 & 3) << 2;
            float4 v = *(const float4*)(X + (size_t)(m0 + row) * IDIM + k0 + c4);
            As[row][c4 + 0] = v.x; As[row][c4 + 1] = v.y;
            As[row][c4 + 2] = v.z; As[row][c4 + 3] = v.w;
        }
#pragma unroll
        for (int i = 0; i < 2; i++) {
            int f4  = tid + i * 256;
            int row = f4 >> 5;
            int c4  = (f4 & 31) << 2;
            *(float4*)&Bs[row][c4] =
                *(const float4*)(Wih + (size_t)(k0 + row) * HDIM + n0 + c4);
        }
        __syncthreads();
#pragma unroll
        for (int k = 0; k < 16; k++) {
            ulonglong2 bv0 = *(const ulonglong2*)&Bs[k][tx * 4];
            ulonglong2 bv1 = *(const ulonglong2*)&Bs[k][64 + tx * 4];
#pragma unroll
            for (int i = 0; i < 8; i++) {
                ull a2 = splat2(As[ty * 8 + i][k]);
                acc[i][0] = ffma2(a2, bv0.x, acc[i][0]);
                acc[i][1] = ffma2(a2, bv0.y, acc[i][1]);
                acc[i][2] = ffma2(a2, bv1.x, acc[i][2]);
                acc[i][3] = ffma2(a2, bv1.y, acc[i][3]);
            }
        }
        __syncthreads();
    }

#pragma unroll
    for (int i = 0; i < 8; i++) {
        float* dst = g_xp + (size_t)(m0 + ty * 8 + i) * HDIM + n0;
#pragma unroll
        for (int j = 0; j < 4; j++) {
            int n = (j < 2) ? (tx * 4 + j * 2) : (64 + tx * 4 + (j - 2) * 2);
            float2 v = upk2(acc[i][j]);
            v.x += bhh[n0 + n];
            v.y += bhh[n0 + n + 1];
            *(float2*)(dst + n) = v;
        }
    }
}

// empty launch to shift ncu's fixed profiled-launch slot onto rnn_kernel
__global__ void dummy_kernel() {}

// ============================================================================
// Kernel B: serial recurrence, producer/consumer warp pipeline.
// 16 clusters x 8 CTAs; rank r owns W_hh cols [64r,64r+64) as ull col-pairs.
// 512 threads: warps 0-7 = consumers (phase1 + phase2 + push), warps 8-15 =
// producers (phase1 only; bar.arrive and run ahead into step t+1).
//
// Partials: consumers -> prtA (single buf, self-ordered); producers ->
// prtB[2] (double buf, they race one step ahead).
// Exchange: consumers stage h into contiguous stg[pb] (2KB); tid<8 bulk-copy
// it to ALL 8 ranks' hx[pb] block (incl. self loopback) with complete_tx to
// per-source mbar (expect 2048 B each). Warp pair (2s,2s+1) waits only mb[s].
// Named barriers: ids 1,2 alternate by step parity (producers arrive,
// consumers sync); id 3 = consumers-only pre-push barrier.
// ============================================================================
#define NT 512
// float offsets
#define OFF_PA  32768                 // ull[8][8][32]     16KB
#define OFF_PB  36864                 // ull[2][8][8][32]  32KB
#define OFF_HX  45056                 // f32[2][8][2][64][4] 32KB
#define OFF_STG 53248                 // f32[2][512]        4KB
#define OFF_MB  54272                 // 16 mbarriers 128B
#define SMEMB_BYTES ((54272 + 32) * 4)
#define BSTRIDE ((size_t)S_LEN * HDIM)
#define BLK_BYTES 2048u

__global__ void __launch_bounds__(NT, 1) __cluster_dims__(8, 1, 1)
rnn_kernel(const float* __restrict__ Whh)
{
    extern __shared__ float sm[];
    ull* Wp   = (ull*)sm;               // [k][jp], k stride 32 ull
    ull* prtA = (ull*)(sm + OFF_PA);    // [w8][b8][jp32]
    ull* prtB = (ull*)(sm + OFF_PB);    // [pb][w8][b8][jp32]

    const int tid  = threadIdx.x;
    const int rank = blockIdx.x & 7;
    const int g    = blockIdx.x >> 3;
    const int c0   = rank * 64;
    const unsigned smb    = s2u32(sm);
    const unsigned mb_loc = smb + OFF_MB * 4;   // mb[src][slot]: +(src*2+slot)*8

    if (tid == 0) {
#pragma unroll
        for (int i = 0; i < 16; i++) {
            mbar_init(mb_loc + i * 8, 1);
            mbar_expect_tx(mb_loc + i * 8, BLK_BYTES);
        }
    }

    // Load W_hh slice once as column pairs (128KB)
    for (int i = tid; i < HDIM * 32; i += NT) {
        int k = i >> 5, jp = i & 31;
        *(float2*)(Wp + i) = *(const float2*)(Whh + (size_t)k * HDIM + c0 + 2 * jp);
    }
    // zero hx (h0 = 0), both slots
    for (int i = tid; i < 2 * 8 * HDIM; i += NT) sm[OFF_HX + i] = 0.f;
    __syncthreads();
    asm volatile("barrier.cluster.arrive.aligned;" ::: "memory");
    asm volatile("barrier.cluster.wait.aligned;"   ::: "memory");

    const int w  = tid >> 5, l = tid & 31;
    const int rg = l >> 4,  ls = l & 15;
    const int kbeg = w * 32;
    const int sw   = w >> 1;            // source rank feeding this warp's k-chunk
    const bool consumer = (w < 8);

    // phase-1 pointers
    const ull*   wsp = Wp + (size_t)kbeg * 32 + ls;
    const float* hxb = sm + OFF_HX + sw * 512 + rg * 256 + (w & 1) * 128;
    ull* pw = (consumer ? prtA + w * 256 : prtB + (w - 8) * 256) + (rg * 4) * 32;

    // consumer (phase-2) pointers: batch b = w, lane l = col-pair jp
    const ull* pA = prtA + w * 32 + l;
    const ull* pB = prtB + w * 32 + l;
    const float* xpp = g_xp + ((size_t)(g * 8 + w)) * BSTRIDE + c0 + 2 * l;
    float*       ghw = g_h  + ((size_t)(g * 8 + w)) * BSTRIDE + c0 + 2 * l;
    float* st0 = sm + OFF_STG + (w >> 2) * 256 + 8 * l + (w & 3);   // + pb*512

    // push targets (tid<8): rank's block in each peer's hx + peer's mb[rank]
    unsigned peer_hx[8], peer_mb[8];
    {
        const unsigned hx0 = smb + (OFF_HX + rank * 512) * 4;
        const unsigned mb0 = mb_loc + (unsigned)(rank * 16);
#pragma unroll
        for (int r = 0; r < 8; r++) {
            peer_hx[r] = mapa_rank(hx0, (unsigned)r);
            peer_mb[r] = mapa_rank(mb0, (unsigned)r);
        }
    }
    const unsigned stg_b  = smb + OFF_STG * 4;
    const unsigned mb_src = mb_loc + (unsigned)(sw * 16);
    const bool rearm_warp = ((w & 1) == 0);

    for (int t = 0; t < S_LEN; t++) {
        const int pb = t & 1, rb = pb ^ 1;

        // xp prefetch (consumers), issued before the wait so it rides it
        ull xv = 0;
        if (consumer) xv = *(const ull*)(xpp + (size_t)t * HDIM);

        // ---- per-source wait: only this warp's source block ----
        if (t > 0) {
            const unsigned mb = mb_src + (unsigned)(rb * 8);
            mbar_wait_parity(mb, (unsigned)(((t - 1) >> 1) & 1));
            if (rearm_warp && elect1()) mbar_expect_tx(mb, BLK_BYTES);
        }

        // ---- phase 1: 2 col-pairs x 4 batches per lane, 32 k ----
        const float* hk = hxb + rb * 4096;
        ull a00 = 0, a01 = 0, a02 = 0, a03 = 0;
        ull a10 = 0, a11 = 0, a12 = 0, a13 = 0;
#pragma unroll 4
        for (int k = 0; k < 32; k++) {
            ull w0 = wsp[k * 32];
            ull w1 = wsp[k * 32 + 16];
            float4 hv = *(const float4*)(hk + k * 4);
            ull h0 = splat2(hv.x), h1 = splat2(hv.y);
            ull h2 = splat2(hv.z), h3 = splat2(hv.w);
            a00 = ffma2(w0, h0, a00);
            a01 = ffma2(w0, h1, a01);
            a02 = ffma2(w0, h2, a02);
            a03 = ffma2(w0, h3, a03);
            a10 = ffma2(w1, h0, a10);
            a11 = ffma2(w1, h1, a11);
            a12 = ffma2(w1, h2, a12);
            a13 = ffma2(w1, h3, a13);
        }
        {
            ull* pq = consumer ? pw : pw + pb * 2048;
            pq[0 * 32 + ls]      = a00;
            pq[1 * 32 + ls]      = a01;
            pq[2 * 32 + ls]      = a02;
            pq[3 * 32 + ls]      = a03;
            pq[0 * 32 + ls + 16] = a10;
            pq[1 * 32 + ls + 16] = a11;
            pq[2 * 32 + ls + 16] = a12;
            pq[3 * 32 + ls + 16] = a13;
        }

        if (!consumer) {
            bar_arrive_512(1u + (unsigned)pb);   // non-blocking; race ahead
            continue;
        }
        bar_sync_512(1u + (unsigned)pb);          // wait all 16 partials

        // ---- phase 2 (consumers): reduce 8A + 8B partials + xp, tanh ----
        {
            const ull* pb8 = pB + pb * 2048;
            ull q0 = add2(pA[0],        pA[256]);
            ull q1 = add2(pA[512],      pA[768]);
            ull q2 = add2(pA[1024],     pA[1280]);
            ull q3 = add2(pA[1536],     pA[1792]);
            ull q4 = add2(pb8[0],       pb8[256]);
            ull q5 = add2(pb8[512],     pb8[768]);
            ull q6 = add2(pb8[1024],    pb8[1280]);
            ull q7 = add2(pb8[1536],    pb8[1792]);
            q0 = add2(q0, q1); q2 = add2(q2, q3);
            q4 = add2(q4, q5); q6 = add2(q6, q7);
            q0 = add2(q0, q2); q4 = add2(q4, q6);
            ull s = add2(xv, add2(q0, q4));
            float2 sv = upk2(s);
            float h0 = tanhf(sv.x);
            float h1 = tanhf(sv.y);
            *(float2*)(ghw + (size_t)t * HDIM) = make_float2(h0, h1);
            if (t == S_LEN - 1) break;           // nobody needs h(S)
            float* st = st0 + pb * 512;
            st[0] = h0;
            st[4] = h1;
        }
        bar_sync_256(3u);                         // staging complete (consumers)

        if (tid < 8) {
            asm volatile("fence.proxy.async.shared::cta;" ::: "memory");
            bulk_s2c(peer_hx[tid] + (unsigned)pb * 16384u,
                     stg_b + (unsigned)pb * 2048u,
                     BLK_BYTES,
                     peer_mb[tid] + (unsigned)pb * 8u);
        }
    }
}

// ============================================================================
// Kernel C: out[M,64] = g_h[M,512] @ W_ho[512,64] + b_ho, M = 131072
// ============================================================================
__global__ void __launch_bounds__(256) out_kernel(
    const float* __restrict__ Who, const float* __restrict__ bho,
    float* __restrict__ out)
{
    __shared__ float As[128][17];
    __shared__ float Bs[16][64];
    const int tid = threadIdx.x;
    const int m0 = blockIdx.x * 128;
    const int tx = tid & 15, ty = tid >> 4;

    ull acc[8][2];
#pragma unroll
    for (int i = 0; i < 8; i++) { acc[i][0] = 0ull; acc[i][1] = 0ull; }

    for (int k0 = 0; k0 < HDIM; k0 += 16) {
#pragma unroll
        for (int i = 0; i < 2; i++) {
            int f4  = tid + i * 256;
            int row = f4 >> 2;
            int c4  = (f4 & 3) << 2;
            float4 v = *(const float4*)(g_h + (size_t)(m0 + row) * HDIM + k0 + c4);
            As[row][c4 + 0] = v.x; As[row][c4 + 1] = v.y;
            As[row][c4 + 2] = v.z; As[row][c4 + 3] = v.w;
        }
        {
            int row = tid >> 4;
            int c4  = (tid & 15) << 2;
            *(float4*)&Bs[row][c4] =
                *(const float4*)(Who + (size_t)(k0 + row) * ODIM + c4);
        }
        __syncthreads();
#pragma unroll
        for (int k = 0; k < 16; k++) {
            ulonglong2 bv = *(const ulonglong2*)&Bs[k][tx * 4];
#pragma unroll
            for (int i = 0; i < 8; i++) {
                ull a2 = splat2(As[ty * 8 + i][k]);
                acc[i][0] = ffma2(a2, bv.x, acc[i][0]);
                acc[i][1] = ffma2(a2, bv.y, acc[i][1]);
            }
        }
        __syncthreads();
    }

    float bb0 = bho[tx * 4 + 0], bb1 = bho[tx * 4 + 1];
    float bb2 = bho[tx * 4 + 2], bb3 = bho[tx * 4 + 3];
#pragma unroll
    for (int i = 0; i < 8; i++) {
        float2 v0 = upk2(acc[i][0]); v0.x += bb0; v0.y += bb1;
        float2 v1 = upk2(acc[i][1]); v1.x += bb2; v1.y += bb3;
        float* dst = out + (size_t)(m0 + ty * 8 + i) * ODIM + tx * 4;
        *(float2*)(dst + 0) = v0;
        *(float2*)(dst + 2) = v1;
    }
}

// ============================================================================
extern "C" void kernel_launch(void* const* d_in, const int* in_sizes, int n_in,
                              void* d_out, int out_size)
{
    const float* X   = (const float*)d_in[0];   // [128,1024,256]
    const float* Whh = (const float*)d_in[1];   // [512,512]
    const float* Wih = (const float*)d_in[2];   // [256,512]
    const float* bhh = (const float*)d_in[3];   // [512]
    const float* Who = (const float*)d_in[4];   // [512,64]
    const float* bho = (const float*)d_in[5];   // [64]
    float* out = (float*)d_out;                 // [128,1024,64]

    cudaFuncSetAttribute(rnn_kernel,
                         cudaFuncAttributeMaxDynamicSharedMemorySize,
                         SMEMB_BYTES);

    xproj_kernel<<<dim3(1024, 4, 1), 256>>>(X, Wih, bhh);
    dummy_kernel<<<1, 32>>>();
    dummy_kernel<<<1, 32>>>();
    rnn_kernel<<<128, NT, SMEMB_BYTES>>>(Whh);
    out_kernel<<<1024, 256>>>(Who, bho, out);
}